// round 1
// baseline (speedup 1.0000x reference)
#include <cuda_runtime.h>
#include <cuda_bf16.h>
#include <math.h>

// Problem constants
constexpr int N_TOK = 16384;
constexpr int DIM   = 2048;
constexpr int NEXP  = 64;
constexpr int TOPK  = 8;

// Scratch (device globals: no runtime allocation allowed)
__device__ float g_H[(size_t)N_TOK * DIM];        // gelu(x@W1+b1), 128 MB
__device__ float g_logits[(size_t)N_TOK * NEXP];  // 4 MB
__device__ float g_probsum[NEXP];
__device__ int   g_cnt[NEXP];

__device__ __forceinline__ float gelu_exact(float x) {
    return 0.5f * x * (1.0f + erff(x * 0.70710678118654752f));
}

// ---------------------------------------------------------------------------
// Kernel 0: zero the small accumulators
// ---------------------------------------------------------------------------
__global__ void k_init() {
    int e = threadIdx.x;
    if (e < NEXP) { g_probsum[e] = 0.0f; g_cnt[e] = 0; }
}

// ---------------------------------------------------------------------------
// Kernel 1: H = gelu(X @ W1 + b1)
// 128x128 tile, BK=16, 256 threads, 8x8 per-thread register tile.
// ---------------------------------------------------------------------------
__global__ __launch_bounds__(256, 2)
void k_gemm1_gelu(const float* __restrict__ X,
                  const float* __restrict__ W1,
                  const float* __restrict__ b1) {
    constexpr int BM = 128, BN = 128, BK = 16;
    __shared__ float As[BK][BM + 4];  // A stored transposed
    __shared__ float Bs[BK][BN];

    const int bm = blockIdx.y * BM;
    const int bn = blockIdx.x * BN;
    const int tid = threadIdx.x;
    const int tx = tid & 15;   // n direction (16 * 8 = 128)
    const int ty = tid >> 4;   // m direction (16 * 8 = 128)

    float acc[8][8];
#pragma unroll
    for (int i = 0; i < 8; ++i)
#pragma unroll
        for (int j = 0; j < 8; ++j) acc[i][j] = 0.0f;

    for (int k0 = 0; k0 < DIM; k0 += BK) {
        // Load A tile: 128 rows x 16 k (512 float4, 2 per thread)
#pragma unroll
        for (int r = 0; r < 2; ++r) {
            int idx = tid + r * 256;
            int m  = idx >> 2;
            int kv = (idx & 3) << 2;
            float4 v = *(const float4*)(X + (size_t)(bm + m) * DIM + k0 + kv);
            As[kv + 0][m] = v.x;
            As[kv + 1][m] = v.y;
            As[kv + 2][m] = v.z;
            As[kv + 3][m] = v.w;
        }
        // Load B tile: 16 k x 128 n (512 float4, 2 per thread)
#pragma unroll
        for (int r = 0; r < 2; ++r) {
            int idx = tid + r * 256;
            int kk = idx >> 5;
            int nv = (idx & 31) << 2;
            *(float4*)&Bs[kk][nv] =
                *(const float4*)(W1 + (size_t)(k0 + kk) * DIM + bn + nv);
        }
        __syncthreads();

#pragma unroll
        for (int kk = 0; kk < BK; ++kk) {
            float a[8], b[8];
            *(float4*)&a[0] = *(const float4*)&As[kk][ty * 8];
            *(float4*)&a[4] = *(const float4*)&As[kk][ty * 8 + 4];
            *(float4*)&b[0] = *(const float4*)&Bs[kk][tx * 8];
            *(float4*)&b[4] = *(const float4*)&Bs[kk][tx * 8 + 4];
#pragma unroll
            for (int i = 0; i < 8; ++i)
#pragma unroll
                for (int j = 0; j < 8; ++j)
                    acc[i][j] = fmaf(a[i], b[j], acc[i][j]);
        }
        __syncthreads();
    }

    // Epilogue: + bias, exact GELU, store
    float bv[8];
    *(float4*)&bv[0] = *(const float4*)(b1 + bn + tx * 8);
    *(float4*)&bv[4] = *(const float4*)(b1 + bn + tx * 8 + 4);
#pragma unroll
    for (int i = 0; i < 8; ++i) {
        size_t row = (size_t)(bm + ty * 8 + i) * DIM + bn + tx * 8;
        float4 o0, o1;
        o0.x = gelu_exact(acc[i][0] + bv[0]);
        o0.y = gelu_exact(acc[i][1] + bv[1]);
        o0.z = gelu_exact(acc[i][2] + bv[2]);
        o0.w = gelu_exact(acc[i][3] + bv[3]);
        o1.x = gelu_exact(acc[i][4] + bv[4]);
        o1.y = gelu_exact(acc[i][5] + bv[5]);
        o1.z = gelu_exact(acc[i][6] + bv[6]);
        o1.w = gelu_exact(acc[i][7] + bv[7]);
        *(float4*)(g_H + row)     = o0;
        *(float4*)(g_H + row + 4) = o1;
    }
}

// ---------------------------------------------------------------------------
// Kernel 2: logits = H @ W2 + b2   ([16384,2048] x [2048,64])
// BM=128 tokens, BN=64 experts, BK=32, 256 threads, 8x4 per-thread tile.
// ---------------------------------------------------------------------------
__global__ __launch_bounds__(256)
void k_gemm2(const float* __restrict__ W2, const float* __restrict__ b2) {
    constexpr int BM = 128, BK = 32;
    __shared__ float As[BK][BM + 4];
    __shared__ float Bs[BK][NEXP];

    const int bm = blockIdx.x * BM;
    const int tid = threadIdx.x;
    const int tx = tid & 15;   // n: 16 * 4 = 64
    const int ty = tid >> 4;   // m: 16 * 8 = 128

    float acc[8][4];
#pragma unroll
    for (int i = 0; i < 8; ++i)
#pragma unroll
        for (int j = 0; j < 4; ++j) acc[i][j] = 0.0f;

    for (int k0 = 0; k0 < DIM; k0 += BK) {
        // A: 128 x 32 = 1024 float4, 4 per thread
#pragma unroll
        for (int r = 0; r < 4; ++r) {
            int idx = tid + r * 256;
            int m  = idx >> 3;
            int kv = (idx & 7) << 2;
            float4 v = *(const float4*)(g_H + (size_t)(bm + m) * DIM + k0 + kv);
            As[kv + 0][m] = v.x;
            As[kv + 1][m] = v.y;
            As[kv + 2][m] = v.z;
            As[kv + 3][m] = v.w;
        }
        // B: 32 x 64 = 512 float4, 2 per thread
#pragma unroll
        for (int r = 0; r < 2; ++r) {
            int idx = tid + r * 256;
            int kk = idx >> 4;
            int nv = (idx & 15) << 2;
            *(float4*)&Bs[kk][nv] =
                *(const float4*)(W2 + (size_t)(k0 + kk) * NEXP + nv);
        }
        __syncthreads();

#pragma unroll
        for (int kk = 0; kk < BK; ++kk) {
            float a[8], b[4];
            *(float4*)&a[0] = *(const float4*)&As[kk][ty * 8];
            *(float4*)&a[4] = *(const float4*)&As[kk][ty * 8 + 4];
            *(float4*)&b[0] = *(const float4*)&Bs[kk][tx * 4];
#pragma unroll
            for (int i = 0; i < 8; ++i)
#pragma unroll
                for (int j = 0; j < 4; ++j)
                    acc[i][j] = fmaf(a[i], b[j], acc[i][j]);
        }
        __syncthreads();
    }

    float4 bb = *(const float4*)(b2 + tx * 4);
#pragma unroll
    for (int i = 0; i < 8; ++i) {
        size_t row = (size_t)(bm + ty * 8 + i) * NEXP + tx * 4;
        float4 o;
        o.x = acc[i][0] + bb.x;
        o.y = acc[i][1] + bb.y;
        o.z = acc[i][2] + bb.z;
        o.w = acc[i][3] + bb.w;
        *(float4*)(g_logits + row) = o;
    }
}

// ---------------------------------------------------------------------------
// Kernel 3: per-token router. One warp per token (8 warps/block).
//  - full softmax -> probsum accumulation (for loss)
//  - top-8 (ties -> lowest index, descending order like jax.lax.top_k)
//  - softmax over top-8 -> routing weights
//  - counts for freq (for loss)
// ---------------------------------------------------------------------------
__global__ __launch_bounds__(256)
void k_router(float* __restrict__ out_rw, float* __restrict__ out_idx,
              int write_idx) {
    __shared__ float psum_sh[NEXP];
    __shared__ int   cnt_sh[NEXP];
    const int tid = threadIdx.x;
    if (tid < NEXP) { psum_sh[tid] = 0.0f; cnt_sh[tid] = 0; }
    __syncthreads();

    const int warp = tid >> 5;
    const int lane = tid & 31;
    const int t = blockIdx.x * 8 + warp;

    float v0 = g_logits[(size_t)t * NEXP + lane];
    float v1 = g_logits[(size_t)t * NEXP + 32 + lane];

    // --- full softmax for load-balance loss ---
    float mx = fmaxf(v0, v1);
#pragma unroll
    for (int o = 16; o; o >>= 1) mx = fmaxf(mx, __shfl_xor_sync(0xffffffffu, mx, o));
    float p0 = expf(v0 - mx);
    float p1 = expf(v1 - mx);
    float s = p0 + p1;
#pragma unroll
    for (int o = 16; o; o >>= 1) s += __shfl_xor_sync(0xffffffffu, s, o);
    float inv = 1.0f / s;
    atomicAdd(&psum_sh[lane],      p0 * inv);
    atomicAdd(&psum_sh[lane + 32], p1 * inv);

    // --- top-8 selection (argmax with lowest-index tie-break, 8 passes) ---
    const float NEG_INF = __int_as_float(0xff800000);
    float w0 = v0, w1 = v1;
    float topv[TOPK];
    int   topi[TOPK];
#pragma unroll
    for (int k = 0; k < TOPK; ++k) {
        float bv; int bi;
        if (w0 >= w1) { bv = w0; bi = lane; }
        else          { bv = w1; bi = lane + 32; }
#pragma unroll
        for (int o = 16; o; o >>= 1) {
            float ov = __shfl_xor_sync(0xffffffffu, bv, o);
            int   oi = __shfl_xor_sync(0xffffffffu, bi, o);
            if (ov > bv || (ov == bv && oi < bi)) { bv = ov; bi = oi; }
        }
        topv[k] = bv;
        topi[k] = bi;
        if (bi == lane)      w0 = NEG_INF;
        if (bi == lane + 32) w1 = NEG_INF;
    }

    // --- softmax over top-8 (topv[0] is the max) ---
    float es[TOPK];
    float ss = 0.0f;
#pragma unroll
    for (int k = 0; k < TOPK; ++k) { es[k] = expf(topv[k] - topv[0]); ss += es[k]; }
    float invs = 1.0f / ss;

    // --- routing weights: each lane owns experts lane, lane+32 ---
    float r0 = 0.0f, r1 = 0.0f;
#pragma unroll
    for (int k = 0; k < TOPK; ++k) {
        float w = es[k] * invs;
        if (topi[k] == lane)      r0 = w;
        if (topi[k] == lane + 32) r1 = w;
    }
    out_rw[(size_t)t * NEXP + lane]      = r0;
    out_rw[(size_t)t * NEXP + 32 + lane] = r1;

    // --- idx output + expert counts (all lanes agree; lane 0 acts) ---
    if (lane == 0) {
#pragma unroll
        for (int k = 0; k < TOPK; ++k) {
            if (write_idx) out_idx[(size_t)t * TOPK + k] = (float)topi[k];
            atomicAdd(&cnt_sh[topi[k]], 1);
        }
    }

    __syncthreads();
    if (tid < NEXP) {
        atomicAdd(&g_probsum[tid], psum_sh[tid]);
        atomicAdd(&g_cnt[tid], cnt_sh[tid]);
    }
}

// ---------------------------------------------------------------------------
// Kernel 4: loss = E * sum_e (cnt_e/N) * (probsum_e/N)
// ---------------------------------------------------------------------------
__global__ void k_loss(float* __restrict__ out_loss) {
    __shared__ float sh[NEXP];
    int e = threadIdx.x;
    float invN = 1.0f / (float)N_TOK;
    sh[e] = ((float)g_cnt[e] * invN) * (g_probsum[e] * invN);
    __syncthreads();
    if (e < 32) sh[e] += sh[e + 32];
    __syncthreads();
    if (e == 0) {
        float acc = 0.0f;
        for (int i = 0; i < 32; ++i) acc += sh[i];
        *out_loss = (float)NEXP * acc;
    }
}

// ---------------------------------------------------------------------------
extern "C" void kernel_launch(void* const* d_in, const int* in_sizes, int n_in,
                              void* d_out, int out_size) {
    const float* x  = (const float*)d_in[0];
    const float* W1 = (const float*)d_in[1];
    const float* b1 = (const float*)d_in[2];
    const float* W2 = (const float*)d_in[3];
    const float* b2 = (const float*)d_in[4];

    float* out = (float*)d_out;
    float* out_rw   = out;
    float* out_idx  = nullptr;
    float* out_loss = nullptr;

    const long rw_elems  = (long)N_TOK * NEXP;         // 1048576
    const long idx_elems = (long)N_TOK * TOPK;         // 131072
    int has_idx = 0;
    if ((long)out_size >= rw_elems + idx_elems) {
        out_idx = out + rw_elems;
        has_idx = 1;
    }
    if ((long)out_size >= rw_elems + idx_elems + 1) {
        out_loss = out + rw_elems + idx_elems;
    }

    k_init<<<1, 64>>>();

    dim3 g1(DIM / 128, N_TOK / 128);
    k_gemm1_gelu<<<g1, 256>>>(x, W1, b1);

    k_gemm2<<<N_TOK / 128, 256>>>(W2, b2);

    k_router<<<N_TOK / 8, 256>>>(out_rw, out_idx, has_idx);

    if (out_loss) k_loss<<<1, 64>>>(out_loss);
}

// round 2
// speedup vs baseline: 1.0010x; 1.0010x over previous
#include <cuda_runtime.h>
#include <cuda_bf16.h>
#include <math.h>

// Problem constants
constexpr int N_TOK = 16384;
constexpr int DIM   = 2048;
constexpr int NEXP  = 64;
constexpr int TOPK  = 8;

// Scratch (device globals: no runtime allocation allowed)
__device__ float g_H[(size_t)N_TOK * DIM];        // gelu(x@W1+b1), 128 MB
__device__ float g_logits[(size_t)N_TOK * NEXP];  // 4 MB
__device__ float g_probsum[NEXP];
__device__ int   g_cnt[NEXP];

__device__ __forceinline__ float gelu_exact(float x) {
    return 0.5f * x * (1.0f + erff(x * 0.70710678118654752f));
}

// ---------------------------------------------------------------------------
// Kernel 0: zero the small accumulators
// ---------------------------------------------------------------------------
__global__ void k_init() {
    int e = threadIdx.x;
    if (e < NEXP) { g_probsum[e] = 0.0f; g_cnt[e] = 0; }
}

// ---------------------------------------------------------------------------
// Kernel 1: H = gelu(X @ W1 + b1)
// 128x128 tile, BK=16, 256 threads, 8x8 per-thread register tile.
// ---------------------------------------------------------------------------
__global__ __launch_bounds__(256, 2)
void k_gemm1_gelu(const float* __restrict__ X,
                  const float* __restrict__ W1,
                  const float* __restrict__ b1) {
    constexpr int BM = 128, BN = 128, BK = 16;
    __shared__ float As[BK][BM + 4];  // A stored transposed
    __shared__ float Bs[BK][BN];

    const int bm = blockIdx.y * BM;
    const int bn = blockIdx.x * BN;
    const int tid = threadIdx.x;
    const int tx = tid & 15;   // n direction (16 * 8 = 128)
    const int ty = tid >> 4;   // m direction (16 * 8 = 128)

    float acc[8][8];
#pragma unroll
    for (int i = 0; i < 8; ++i)
#pragma unroll
        for (int j = 0; j < 8; ++j) acc[i][j] = 0.0f;

    for (int k0 = 0; k0 < DIM; k0 += BK) {
        // Load A tile: 128 rows x 16 k (512 float4, 2 per thread)
#pragma unroll
        for (int r = 0; r < 2; ++r) {
            int idx = tid + r * 256;
            int m  = idx >> 2;
            int kv = (idx & 3) << 2;
            float4 v = *(const float4*)(X + (size_t)(bm + m) * DIM + k0 + kv);
            As[kv + 0][m] = v.x;
            As[kv + 1][m] = v.y;
            As[kv + 2][m] = v.z;
            As[kv + 3][m] = v.w;
        }
        // Load B tile: 16 k x 128 n (512 float4, 2 per thread)
#pragma unroll
        for (int r = 0; r < 2; ++r) {
            int idx = tid + r * 256;
            int kk = idx >> 5;
            int nv = (idx & 31) << 2;
            *(float4*)&Bs[kk][nv] =
                *(const float4*)(W1 + (size_t)(k0 + kk) * DIM + bn + nv);
        }
        __syncthreads();

#pragma unroll
        for (int kk = 0; kk < BK; ++kk) {
            float a[8], b[8];
            *(float4*)&a[0] = *(const float4*)&As[kk][ty * 8];
            *(float4*)&a[4] = *(const float4*)&As[kk][ty * 8 + 4];
            *(float4*)&b[0] = *(const float4*)&Bs[kk][tx * 8];
            *(float4*)&b[4] = *(const float4*)&Bs[kk][tx * 8 + 4];
#pragma unroll
            for (int i = 0; i < 8; ++i)
#pragma unroll
                for (int j = 0; j < 8; ++j)
                    acc[i][j] = fmaf(a[i], b[j], acc[i][j]);
        }
        __syncthreads();
    }

    // Epilogue: + bias, exact GELU, store
    float bv[8];
    *(float4*)&bv[0] = *(const float4*)(b1 + bn + tx * 8);
    *(float4*)&bv[4] = *(const float4*)(b1 + bn + tx * 8 + 4);
#pragma unroll
    for (int i = 0; i < 8; ++i) {
        size_t row = (size_t)(bm + ty * 8 + i) * DIM + bn + tx * 8;
        float4 o0, o1;
        o0.x = gelu_exact(acc[i][0] + bv[0]);
        o0.y = gelu_exact(acc[i][1] + bv[1]);
        o0.z = gelu_exact(acc[i][2] + bv[2]);
        o0.w = gelu_exact(acc[i][3] + bv[3]);
        o1.x = gelu_exact(acc[i][4] + bv[4]);
        o1.y = gelu_exact(acc[i][5] + bv[5]);
        o1.z = gelu_exact(acc[i][6] + bv[6]);
        o1.w = gelu_exact(acc[i][7] + bv[7]);
        *(float4*)(g_H + row)     = o0;
        *(float4*)(g_H + row + 4) = o1;
    }
}

// ---------------------------------------------------------------------------
// Kernel 2: logits = H @ W2 + b2   ([16384,2048] x [2048,64])
// BM=128 tokens, BN=64 experts, BK=32, 256 threads, 8x4 per-thread tile.
// ---------------------------------------------------------------------------
__global__ __launch_bounds__(256)
void k_gemm2(const float* __restrict__ W2, const float* __restrict__ b2) {
    constexpr int BM = 128, BK = 32;
    __shared__ float As[BK][BM + 4];
    __shared__ float Bs[BK][NEXP];

    const int bm = blockIdx.x * BM;
    const int tid = threadIdx.x;
    const int tx = tid & 15;   // n: 16 * 4 = 64
    const int ty = tid >> 4;   // m: 16 * 8 = 128

    float acc[8][4];
#pragma unroll
    for (int i = 0; i < 8; ++i)
#pragma unroll
        for (int j = 0; j < 4; ++j) acc[i][j] = 0.0f;

    for (int k0 = 0; k0 < DIM; k0 += BK) {
        // A: 128 x 32 = 1024 float4, 4 per thread
#pragma unroll
        for (int r = 0; r < 4; ++r) {
            int idx = tid + r * 256;
            int m  = idx >> 3;
            int kv = (idx & 7) << 2;
            float4 v = *(const float4*)(g_H + (size_t)(bm + m) * DIM + k0 + kv);
            As[kv + 0][m] = v.x;
            As[kv + 1][m] = v.y;
            As[kv + 2][m] = v.z;
            As[kv + 3][m] = v.w;
        }
        // B: 32 x 64 = 512 float4, 2 per thread
#pragma unroll
        for (int r = 0; r < 2; ++r) {
            int idx = tid + r * 256;
            int kk = idx >> 4;
            int nv = (idx & 15) << 2;
            *(float4*)&Bs[kk][nv] =
                *(const float4*)(W2 + (size_t)(k0 + kk) * NEXP + nv);
        }
        __syncthreads();

#pragma unroll
        for (int kk = 0; kk < BK; ++kk) {
            float a[8], b[4];
            *(float4*)&a[0] = *(const float4*)&As[kk][ty * 8];
            *(float4*)&a[4] = *(const float4*)&As[kk][ty * 8 + 4];
            *(float4*)&b[0] = *(const float4*)&Bs[kk][tx * 4];
#pragma unroll
            for (int i = 0; i < 8; ++i)
#pragma unroll
                for (int j = 0; j < 4; ++j)
                    acc[i][j] = fmaf(a[i], b[j], acc[i][j]);
        }
        __syncthreads();
    }

    float4 bb = *(const float4*)(b2 + tx * 4);
#pragma unroll
    for (int i = 0; i < 8; ++i) {
        size_t row = (size_t)(bm + ty * 8 + i) * NEXP + tx * 4;
        float4 o;
        o.x = acc[i][0] + bb.x;
        o.y = acc[i][1] + bb.y;
        o.z = acc[i][2] + bb.z;
        o.w = acc[i][3] + bb.w;
        *(float4*)(g_logits + row) = o;
    }
}

// ---------------------------------------------------------------------------
// Kernel 3: per-token router. One warp per token (8 warps/block).
//  - full softmax -> probsum accumulation (for loss)
//  - top-8 (ties -> lowest index, descending order like jax.lax.top_k)
//  - softmax over top-8 -> routing weights
//  - counts for freq (for loss)
// ---------------------------------------------------------------------------
__global__ __launch_bounds__(256)
void k_router(float* __restrict__ out_rw, float* __restrict__ out_idx,
              int write_idx) {
    __shared__ float psum_sh[NEXP];
    __shared__ int   cnt_sh[NEXP];
    const int tid = threadIdx.x;
    if (tid < NEXP) { psum_sh[tid] = 0.0f; cnt_sh[tid] = 0; }
    __syncthreads();

    const int warp = tid >> 5;
    const int lane = tid & 31;
    const int t = blockIdx.x * 8 + warp;

    float v0 = g_logits[(size_t)t * NEXP + lane];
    float v1 = g_logits[(size_t)t * NEXP + 32 + lane];

    // --- full softmax for load-balance loss ---
    float mx = fmaxf(v0, v1);
#pragma unroll
    for (int o = 16; o; o >>= 1) mx = fmaxf(mx, __shfl_xor_sync(0xffffffffu, mx, o));
    float p0 = expf(v0 - mx);
    float p1 = expf(v1 - mx);
    float s = p0 + p1;
#pragma unroll
    for (int o = 16; o; o >>= 1) s += __shfl_xor_sync(0xffffffffu, s, o);
    float inv = 1.0f / s;
    atomicAdd(&psum_sh[lane],      p0 * inv);
    atomicAdd(&psum_sh[lane + 32], p1 * inv);

    // --- top-8 selection (argmax with lowest-index tie-break, 8 passes) ---
    const float NEG_INF = __int_as_float(0xff800000);
    float w0 = v0, w1 = v1;
    float topv[TOPK];
    int   topi[TOPK];
#pragma unroll
    for (int k = 0; k < TOPK; ++k) {
        float bv; int bi;
        if (w0 >= w1) { bv = w0; bi = lane; }
        else          { bv = w1; bi = lane + 32; }
#pragma unroll
        for (int o = 16; o; o >>= 1) {
            float ov = __shfl_xor_sync(0xffffffffu, bv, o);
            int   oi = __shfl_xor_sync(0xffffffffu, bi, o);
            if (ov > bv || (ov == bv && oi < bi)) { bv = ov; bi = oi; }
        }
        topv[k] = bv;
        topi[k] = bi;
        if (bi == lane)      w0 = NEG_INF;
        if (bi == lane + 32) w1 = NEG_INF;
    }

    // --- softmax over top-8 (topv[0] is the max) ---
    float es[TOPK];
    float ss = 0.0f;
#pragma unroll
    for (int k = 0; k < TOPK; ++k) { es[k] = expf(topv[k] - topv[0]); ss += es[k]; }
    float invs = 1.0f / ss;

    // --- routing weights: each lane owns experts lane, lane+32 ---
    float r0 = 0.0f, r1 = 0.0f;
#pragma unroll
    for (int k = 0; k < TOPK; ++k) {
        float w = es[k] * invs;
        if (topi[k] == lane)      r0 = w;
        if (topi[k] == lane + 32) r1 = w;
    }
    out_rw[(size_t)t * NEXP + lane]      = r0;
    out_rw[(size_t)t * NEXP + 32 + lane] = r1;

    // --- idx output + expert counts (all lanes agree; lane 0 acts) ---
    if (lane == 0) {
#pragma unroll
        for (int k = 0; k < TOPK; ++k) {
            if (write_idx) out_idx[(size_t)t * TOPK + k] = (float)topi[k];
            atomicAdd(&cnt_sh[topi[k]], 1);
        }
    }

    __syncthreads();
    if (tid < NEXP) {
        atomicAdd(&g_probsum[tid], psum_sh[tid]);
        atomicAdd(&g_cnt[tid], cnt_sh[tid]);
    }
}

// ---------------------------------------------------------------------------
// Kernel 4: loss = E * sum_e (cnt_e/N) * (probsum_e/N)
// ---------------------------------------------------------------------------
__global__ void k_loss(float* __restrict__ out_loss) {
    __shared__ float sh[NEXP];
    int e = threadIdx.x;
    float invN = 1.0f / (float)N_TOK;
    sh[e] = ((float)g_cnt[e] * invN) * (g_probsum[e] * invN);
    __syncthreads();
    if (e < 32) sh[e] += sh[e + 32];
    __syncthreads();
    if (e == 0) {
        float acc = 0.0f;
        for (int i = 0; i < 32; ++i) acc += sh[i];
        *out_loss = (float)NEXP * acc;
    }
}

// ---------------------------------------------------------------------------
extern "C" void kernel_launch(void* const* d_in, const int* in_sizes, int n_in,
                              void* d_out, int out_size) {
    const float* x  = (const float*)d_in[0];
    const float* W1 = (const float*)d_in[1];
    const float* b1 = (const float*)d_in[2];
    const float* W2 = (const float*)d_in[3];
    const float* b2 = (const float*)d_in[4];

    float* out = (float*)d_out;
    float* out_rw   = out;
    float* out_idx  = nullptr;
    float* out_loss = nullptr;

    const long rw_elems  = (long)N_TOK * NEXP;         // 1048576
    const long idx_elems = (long)N_TOK * TOPK;         // 131072
    int has_idx = 0;
    if ((long)out_size >= rw_elems + idx_elems) {
        out_idx = out + rw_elems;
        has_idx = 1;
    }
    if ((long)out_size >= rw_elems + idx_elems + 1) {
        out_loss = out + rw_elems + idx_elems;
    }

    k_init<<<1, 64>>>();

    dim3 g1(DIM / 128, N_TOK / 128);
    k_gemm1_gelu<<<g1, 256>>>(x, W1, b1);

    k_gemm2<<<N_TOK / 128, 256>>>(W2, b2);

    k_router<<<N_TOK / 8, 256>>>(out_rw, out_idx, has_idx);

    if (out_loss) k_loss<<<1, 64>>>(out_loss);
}

// round 4
// speedup vs baseline: 2.5234x; 2.5207x over previous
#include <cuda_runtime.h>
#include <cuda_fp16.h>
#include <math.h>
#include <stdint.h>

constexpr int N_TOK = 16384;
constexpr int DIM   = 2048;
constexpr int NEXP  = 64;
constexpr int TOPK  = 8;
constexpr int KCH   = 32;          // K per stage
constexpr int NS    = DIM / KCH;   // 64 stages

// scales: X,H pre-scaled by 16; W1,W2 by 64; product scale 1024
constexpr float SCL_A  = 16.0f;
constexpr float SCL_B  = 64.0f;
constexpr float INV_SC = 1.0f / 1024.0f;

// ---------------- device scratch ----------------
__device__ __half g_Xs0[(size_t)N_TOK * DIM];
__device__ __half g_Xs1[(size_t)N_TOK * DIM];
__device__ __half g_Hs0[(size_t)N_TOK * DIM];
__device__ __half g_Hs1[(size_t)N_TOK * DIM];
__device__ __half g_W1T0[(size_t)DIM * DIM];   // [n][k]
__device__ __half g_W1T1[(size_t)DIM * DIM];
__device__ __half g_W2T0[(size_t)NEXP * DIM];  // [e][k]
__device__ __half g_W2T1[(size_t)NEXP * DIM];
__device__ float g_logits[(size_t)N_TOK * NEXP];
__device__ float g_probsum[NEXP];
__device__ int   g_cnt[NEXP];

// ---------------- helpers ----------------
__device__ __forceinline__ float gelu_exact(float x) {
    return 0.5f * x * (1.0f + erff(x * 0.70710678118654752f));
}
__device__ __forceinline__ uint32_t smem_u32(const void* p) {
    uint32_t a;
    asm("{ .reg .u64 t; cvta.to.shared.u64 t, %1; cvt.u32.u64 %0, t; }" : "=r"(a) : "l"(p));
    return a;
}
__device__ __forceinline__ void cpa16(uint32_t dst, const void* src) {
    asm volatile("cp.async.cg.shared.global [%0], [%1], 16;" :: "r"(dst), "l"(src) : "memory");
}
__device__ __forceinline__ void cp_commit() {
    asm volatile("cp.async.commit_group;" ::: "memory");
}
__device__ __forceinline__ void cp_wait1() {
    asm volatile("cp.async.wait_group 1;" ::: "memory");
}
__device__ __forceinline__ void ldsm4(uint32_t* r, uint32_t a) {
    asm volatile("ldmatrix.sync.aligned.m8n8.x4.shared.b16 {%0,%1,%2,%3}, [%4];"
                 : "=r"(r[0]), "=r"(r[1]), "=r"(r[2]), "=r"(r[3]) : "r"(a));
}
__device__ __forceinline__ void mma16816(float* c, const uint32_t* a, const uint32_t* b) {
    asm volatile("mma.sync.aligned.m16n8k16.row.col.f32.f16.f16.f32 "
                 "{%0,%1,%2,%3}, {%4,%5,%6,%7}, {%8,%9}, {%0,%1,%2,%3};"
                 : "+f"(c[0]), "+f"(c[1]), "+f"(c[2]), "+f"(c[3])
                 : "r"(a[0]), "r"(a[1]), "r"(a[2]), "r"(a[3]), "r"(b[0]), "r"(b[1]));
}
__device__ __forceinline__ void split2(float v, __half& h0, __half& h1) {
    h0 = __float2half_rn(v);
    h1 = __float2half_rn(v - __half2float(h0));
}

// ---------------- init / split kernels ----------------
__global__ void k_init() {
    int e = threadIdx.x;
    if (e < NEXP) { g_probsum[e] = 0.0f; g_cnt[e] = 0; }
}

__global__ __launch_bounds__(256) void k_split_X(const float* __restrict__ x) {
    const size_t total = (size_t)N_TOK * DIM / 4;
    for (size_t i = (size_t)blockIdx.x * blockDim.x + threadIdx.x; i < total;
         i += (size_t)gridDim.x * blockDim.x) {
        float4 v = ((const float4*)x)[i];
        __half a0, a1, b0, b1, c0, c1, d0, d1;
        split2(SCL_A * v.x, a0, a1); split2(SCL_A * v.y, b0, b1);
        split2(SCL_A * v.z, c0, c1); split2(SCL_A * v.w, d0, d1);
        __half2 p0a = __halves2half2(a0, b0), p0b = __halves2half2(c0, d0);
        __half2 p1a = __halves2half2(a1, b1), p1b = __halves2half2(c1, d1);
        ((uint2*)g_Xs0)[i] = make_uint2(*(uint32_t*)&p0a, *(uint32_t*)&p0b);
        ((uint2*)g_Xs1)[i] = make_uint2(*(uint32_t*)&p1a, *(uint32_t*)&p1b);
    }
}

// transpose + split: src[R][C] row-major -> dst[C][R] as 2 fp16 splits (scaled)
__global__ void k_split_T(const float* __restrict__ src,
                          __half* __restrict__ d0, __half* __restrict__ d1,
                          int R, int C) {
    __shared__ float t[32][33];
    int bx = blockIdx.x * 32, by = blockIdx.y * 32;
    int tx = threadIdx.x, ty = threadIdx.y;
#pragma unroll
    for (int i = 0; i < 32; i += 8)
        t[ty + i][tx] = src[(size_t)(by + ty + i) * C + bx + tx];
    __syncthreads();
#pragma unroll
    for (int i = 0; i < 32; i += 8) {
        float v = SCL_B * t[tx][ty + i];
        __half s0, s1; split2(v, s0, s1);
        size_t o = (size_t)(bx + ty + i) * R + by + tx;
        d0[o] = s0; d1[o] = s1;
    }
}

// ---------------- HMMA GEMM ----------------
// MODE 0: H = gelu(X@W1 + b1), BN=128. MODE 1: logits = H@W2 + b2, BN=64.
// C = A0*B0 + A0*B1 + A1*B0  (fp16 2-split, fp32 accum)
template <int BN, int MODE>
__global__ __launch_bounds__(256, 2) void k_mma(const float* __restrict__ bias) {
    constexpr int ROWB = 80;                 // padded row bytes (32 halves + 16B pad)
    constexpr int SA_B = 128 * ROWB;         // 10240
    constexpr int SB_B = BN * ROWB;
    constexpr int STGB = 2 * SA_B + 2 * SB_B;
    constexpr int NT   = BN / 32;            // n-tiles per warp (4 or 2)
    constexpr int NP   = NT / 2;             // ldsm x4 B loads per kstep

    extern __shared__ char sm[];
    const int tid = threadIdx.x, wid = tid >> 5, lane = tid & 31;
    const int warp_m = wid >> 2;             // 0..1
    const int warp_n = wid & 3;              // 0..3
    const int bm = (MODE == 0 ? blockIdx.y : blockIdx.x) * 128;
    const int bn = (MODE == 0 ? blockIdx.x * BN : 0);
    const uint32_t smb = smem_u32(sm);

    const __half* pA0 = (MODE == 0) ? g_Xs0 : g_Hs0;
    const __half* pA1 = (MODE == 0) ? g_Xs1 : g_Hs1;
    const __half* pB0 = (MODE == 0) ? g_W1T0 : g_W2T0;
    const __half* pB1 = (MODE == 0) ? g_W1T1 : g_W2T1;

    // per-lane ldmatrix address offsets (bytes)
    const int lr = lane & 7, lg = lane >> 3;
    const uint32_t a_off = (uint32_t)((lr + (lg & 1) * 8) * ROWB + (lg >> 1) * 16);
    const uint32_t b_off = (uint32_t)((lr + (lg >> 1) * 8) * ROWB + (lg & 1) * 16);

    float acc[4][NT][4];
#pragma unroll
    for (int i = 0; i < 4; ++i)
#pragma unroll
        for (int j = 0; j < NT; ++j)
#pragma unroll
            for (int e = 0; e < 4; ++e) acc[i][j][e] = 0.0f;

    auto load_stage = [&](int s) {
        const int k0 = s * KCH;
        const uint32_t base = smb + (uint32_t)((s & 1) * STGB);
        constexpr int CH_A = 2 * 128 * 4;    // 1024
        constexpr int CH_B = 2 * BN * 4;
#pragma unroll
        for (int t = tid; t < CH_A + CH_B; t += 256) {
            if (t < CH_A) {
                int sp = t >> 9, idx = t & 511;
                int r = idx >> 2, c = idx & 3;
                const __half* src = (sp == 0 ? pA0 : pA1) + (size_t)(bm + r) * DIM + k0 + c * 8;
                cpa16(base + (uint32_t)(sp * SA_B + r * ROWB + c * 16), src);
            } else {
                int u = t - CH_A;
                int sp = u / (BN * 4), idx = u % (BN * 4);
                int r = idx >> 2, c = idx & 3;
                const __half* src = (sp == 0 ? pB0 : pB1) + (size_t)(bn + r) * DIM + k0 + c * 8;
                cpa16(base + (uint32_t)(2 * SA_B + sp * SB_B + r * ROWB + c * 16), src);
            }
        }
        cp_commit();
    };

    load_stage(0);
    load_stage(1);

    for (int s = 0; s < NS; ++s) {
        cp_wait1();
        __syncthreads();

        const uint32_t base = smb + (uint32_t)((s & 1) * STGB);
        const uint32_t aBase = base + a_off + (uint32_t)(warp_m * 64 * ROWB);
        const uint32_t bBase = base + 2 * SA_B + b_off + (uint32_t)(warp_n * (BN / 4) * ROWB);

        uint32_t af[4][4], bf[NP][4];
#pragma unroll
        for (int ks = 0; ks < 2; ++ks) {
            const uint32_t kb = (uint32_t)(ks * 32);  // 16 halves = 32 bytes
            // B0 fragments
#pragma unroll
            for (int np = 0; np < NP; ++np)
                ldsm4(bf[np], bBase + (uint32_t)(np * 16 * ROWB) + kb);
            // A0, product hh
#pragma unroll
            for (int mt = 0; mt < 4; ++mt)
                ldsm4(af[mt], aBase + (uint32_t)(mt * 16 * ROWB) + kb);
#pragma unroll
            for (int mt = 0; mt < 4; ++mt)
#pragma unroll
                for (int nt = 0; nt < NT; ++nt)
                    mma16816(acc[mt][nt], af[mt], &bf[nt >> 1][(nt & 1) * 2]);
            // A1, product lh (A1*B0)
#pragma unroll
            for (int mt = 0; mt < 4; ++mt)
                ldsm4(af[mt], aBase + (uint32_t)(SA_B + mt * 16 * ROWB) + kb);
#pragma unroll
            for (int mt = 0; mt < 4; ++mt)
#pragma unroll
                for (int nt = 0; nt < NT; ++nt)
                    mma16816(acc[mt][nt], af[mt], &bf[nt >> 1][(nt & 1) * 2]);
            // B1 fragments, A0 again, product hl (A0*B1)
#pragma unroll
            for (int np = 0; np < NP; ++np)
                ldsm4(bf[np], bBase + (uint32_t)(SB_B + np * 16 * ROWB) + kb);
#pragma unroll
            for (int mt = 0; mt < 4; ++mt)
                ldsm4(af[mt], aBase + (uint32_t)(mt * 16 * ROWB) + kb);
#pragma unroll
            for (int mt = 0; mt < 4; ++mt)
#pragma unroll
                for (int nt = 0; nt < NT; ++nt)
                    mma16816(acc[mt][nt], af[mt], &bf[nt >> 1][(nt & 1) * 2]);
        }

        __syncthreads();
        if (s + 2 < NS) load_stage(s + 2);
        else cp_commit();   // keep group count aligned
    }

    // ---------------- epilogue ----------------
#pragma unroll
    for (int mt = 0; mt < 4; ++mt) {
        const int r0 = bm + warp_m * 64 + mt * 16 + (lane >> 2);
        const int r1 = r0 + 8;
#pragma unroll
        for (int nt = 0; nt < NT; ++nt) {
            const int cl = warp_n * (BN / 4) + nt * 8 + ((lane & 3) << 1);
            const int cg = bn + cl;
            const float bv0 = __ldg(bias + cg), bv1 = __ldg(bias + cg + 1);
            float v00 = acc[mt][nt][0] * INV_SC + bv0;
            float v01 = acc[mt][nt][1] * INV_SC + bv1;
            float v10 = acc[mt][nt][2] * INV_SC + bv0;
            float v11 = acc[mt][nt][3] * INV_SC + bv1;
            if (MODE == 0) {
                v00 = SCL_A * gelu_exact(v00); v01 = SCL_A * gelu_exact(v01);
                v10 = SCL_A * gelu_exact(v10); v11 = SCL_A * gelu_exact(v11);
                __half h00a, h00b, h01a, h01b, h10a, h10b, h11a, h11b;
                split2(v00, h00a, h00b); split2(v01, h01a, h01b);
                split2(v10, h10a, h10b); split2(v11, h11a, h11b);
                *(__half2*)(g_Hs0 + (size_t)r0 * DIM + cg) = __halves2half2(h00a, h01a);
                *(__half2*)(g_Hs1 + (size_t)r0 * DIM + cg) = __halves2half2(h00b, h01b);
                *(__half2*)(g_Hs0 + (size_t)r1 * DIM + cg) = __halves2half2(h10a, h11a);
                *(__half2*)(g_Hs1 + (size_t)r1 * DIM + cg) = __halves2half2(h10b, h11b);
            } else {
                *(float2*)(g_logits + (size_t)r0 * NEXP + cl) = make_float2(v00, v01);
                *(float2*)(g_logits + (size_t)r1 * NEXP + cl) = make_float2(v10, v11);
            }
        }
    }
}

// ---------------- router + loss ----------------
__global__ __launch_bounds__(256)
void k_router(float* __restrict__ out_rw, float* __restrict__ out_idx, int write_idx) {
    __shared__ float psum_sh[NEXP];
    __shared__ int   cnt_sh[NEXP];
    const int tid = threadIdx.x;
    if (tid < NEXP) { psum_sh[tid] = 0.0f; cnt_sh[tid] = 0; }
    __syncthreads();

    const int warp = tid >> 5, lane = tid & 31;
    const int t = blockIdx.x * 8 + warp;
    float v0 = g_logits[(size_t)t * NEXP + lane];
    float v1 = g_logits[(size_t)t * NEXP + 32 + lane];

    float mx = fmaxf(v0, v1);
#pragma unroll
    for (int o = 16; o; o >>= 1) mx = fmaxf(mx, __shfl_xor_sync(0xffffffffu, mx, o));
    float p0 = expf(v0 - mx), p1 = expf(v1 - mx);
    float s = p0 + p1;
#pragma unroll
    for (int o = 16; o; o >>= 1) s += __shfl_xor_sync(0xffffffffu, s, o);
    float inv = 1.0f / s;
    atomicAdd(&psum_sh[lane], p0 * inv);
    atomicAdd(&psum_sh[lane + 32], p1 * inv);

    const float NEG_INF = __int_as_float(0xff800000);
    float w0 = v0, w1 = v1;
    float topv[TOPK]; int topi[TOPK];
#pragma unroll
    for (int k = 0; k < TOPK; ++k) {
        float bv; int bi;
        if (w0 >= w1) { bv = w0; bi = lane; } else { bv = w1; bi = lane + 32; }
#pragma unroll
        for (int o = 16; o; o >>= 1) {
            float ov = __shfl_xor_sync(0xffffffffu, bv, o);
            int   oi = __shfl_xor_sync(0xffffffffu, bi, o);
            if (ov > bv || (ov == bv && oi < bi)) { bv = ov; bi = oi; }
        }
        topv[k] = bv; topi[k] = bi;
        if (bi == lane) w0 = NEG_INF;
        if (bi == lane + 32) w1 = NEG_INF;
    }
    float es[TOPK], ss = 0.0f;
#pragma unroll
    for (int k = 0; k < TOPK; ++k) { es[k] = expf(topv[k] - topv[0]); ss += es[k]; }
    float invs = 1.0f / ss;
    float r0 = 0.0f, r1 = 0.0f;
#pragma unroll
    for (int k = 0; k < TOPK; ++k) {
        float w = es[k] * invs;
        if (topi[k] == lane) r0 = w;
        if (topi[k] == lane + 32) r1 = w;
    }
    out_rw[(size_t)t * NEXP + lane] = r0;
    out_rw[(size_t)t * NEXP + 32 + lane] = r1;

    if (lane == 0) {
#pragma unroll
        for (int k = 0; k < TOPK; ++k) {
            if (write_idx) out_idx[(size_t)t * TOPK + k] = (float)topi[k];
            atomicAdd(&cnt_sh[topi[k]], 1);
        }
    }
    __syncthreads();
    if (tid < NEXP) {
        atomicAdd(&g_probsum[tid], psum_sh[tid]);
        atomicAdd(&g_cnt[tid], cnt_sh[tid]);
    }
}

__global__ void k_loss(float* __restrict__ out_loss) {
    __shared__ float sh[NEXP];
    int e = threadIdx.x;
    float invN = 1.0f / (float)N_TOK;
    sh[e] = ((float)g_cnt[e] * invN) * (g_probsum[e] * invN);
    __syncthreads();
    if (e < 32) sh[e] += sh[e + 32];
    __syncthreads();
    if (e == 0) {
        float acc = 0.0f;
        for (int i = 0; i < 32; ++i) acc += sh[i];
        *out_loss = (float)NEXP * acc;
    }
}

// ---------------- host launch ----------------
extern "C" void kernel_launch(void* const* d_in, const int* in_sizes, int n_in,
                              void* d_out, int out_size) {
    const float* x  = (const float*)d_in[0];
    const float* W1 = (const float*)d_in[1];
    const float* b1 = (const float*)d_in[2];
    const float* W2 = (const float*)d_in[3];
    const float* b2 = (const float*)d_in[4];

    float* out = (float*)d_out;
    float* out_rw = out;
    float* out_idx = nullptr;
    float* out_loss = nullptr;
    const long rw_elems = (long)N_TOK * NEXP;
    const long idx_elems = (long)N_TOK * TOPK;
    int has_idx = 0;
    if ((long)out_size >= rw_elems + idx_elems) { out_idx = out + rw_elems; has_idx = 1; }
    if ((long)out_size >= rw_elems + idx_elems + 1) out_loss = out + rw_elems + idx_elems;

    constexpr int SM1 = 2 * (2 * 128 * 80 + 2 * 128 * 80);  // 81920
    constexpr int SM2 = 2 * (2 * 128 * 80 + 2 * 64 * 80);   // 61440
    static int attr_done = 0;
    if (!attr_done) {
        cudaFuncSetAttribute(k_mma<128, 0>, cudaFuncAttributeMaxDynamicSharedMemorySize, SM1);
        cudaFuncSetAttribute(k_mma<64, 1>,  cudaFuncAttributeMaxDynamicSharedMemorySize, SM2);
        attr_done = 1;
    }

    __half *w1t0, *w1t1, *w2t0, *w2t1;
    cudaGetSymbolAddress((void**)&w1t0, g_W1T0);
    cudaGetSymbolAddress((void**)&w1t1, g_W1T1);
    cudaGetSymbolAddress((void**)&w2t0, g_W2T0);
    cudaGetSymbolAddress((void**)&w2t1, g_W2T1);

    k_init<<<1, 64>>>();
    k_split_X<<<4096, 256>>>(x);
    k_split_T<<<dim3(64, 64), dim3(32, 8)>>>(W1, w1t0, w1t1, DIM, DIM);
    k_split_T<<<dim3(2, 64), dim3(32, 8)>>>(W2, w2t0, w2t1, DIM, NEXP);

    k_mma<128, 0><<<dim3(16, 128), 256, SM1>>>(b1);
    k_mma<64, 1><<<dim3(128), 256, SM2>>>(b2);

    k_router<<<N_TOK / 8, 256>>>(out_rw, out_idx, has_idx);
    if (out_loss) k_loss<<<1, 64>>>(out_loss);
}